// round 1
// baseline (speedup 1.0000x reference)
#include <cuda_runtime.h>
#include <cuda_bf16.h>
#include <math.h>

// Problem constants
#define HID 1024
#define NH  16
#define HD  64
#define BB  4
#define TT  2048
#define RR  8
#define SCALING 2.0f

// Scratch (device globals; no allocation allowed)
__device__ float g_Weff[3 * HID * HID];                      // [3*1024][1024] row-major, row=c=(mat*1024+o)
__device__ float g_QKV[3 * BB * NH * TT * HD];               // [(mat*4+b)*16+h][t][d]

// ---------------------------------------------------------------------------
// Kernel 1: fold LoRA into dense weights: Weff[o][i] = W[o][i] + 2 * sum_r B[o][r]*A[r][i]
// ---------------------------------------------------------------------------
__global__ void fold_lora_kernel(const float* __restrict__ W0, const float* __restrict__ A0, const float* __restrict__ B0,
                                 const float* __restrict__ W1, const float* __restrict__ A1, const float* __restrict__ B1,
                                 const float* __restrict__ W2, const float* __restrict__ A2, const float* __restrict__ B2) {
    int idx = blockIdx.x * blockDim.x + threadIdx.x;
    if (idx >= 3 * HID * HID) return;
    int mat = idx >> 20;
    int oi  = idx & (HID * HID - 1);
    int o   = oi >> 10;
    int i   = oi & 1023;
    const float* W = (mat == 0) ? W0 : (mat == 1) ? W1 : W2;
    const float* A = (mat == 0) ? A0 : (mat == 1) ? A1 : A2;
    const float* Bm = (mat == 0) ? B0 : (mat == 1) ? B1 : B2;
    float acc = W[oi];
#pragma unroll
    for (int r = 0; r < RR; r++)
        acc += SCALING * Bm[o * RR + r] * A[r * HID + i];
    g_Weff[idx] = acc;
}

// ---------------------------------------------------------------------------
// Kernel 2: QKV GEMM. out[m][c] = sum_k X[m][k] * Weff[c][k] + bias[c]
// M = 8192, N = 3072, K = 1024. 64x64 block tile, BK=16, 4x4 per thread (256 thr).
// Epilogue scatters to g_QKV in [mat][b][h][t][d] layout.
// ---------------------------------------------------------------------------
#define GBK 16
__global__ void qkv_gemm_kernel(const float* __restrict__ X,
                                const float* __restrict__ bq,
                                const float* __restrict__ bk,
                                const float* __restrict__ bv) {
    __shared__ float As[GBK * 68];   // [k][m], stride 68
    __shared__ float Bs[GBK * 68];   // [k][c], stride 68

    int tid = threadIdx.x;
    int tx = tid & 15;          // col group
    int ty = tid >> 4;          // row group
    int m0 = blockIdx.y * 64;
    int c0 = blockIdx.x * 64;

    // loader indices: each thread loads one float4 of A and one of B per ktile
    int lm = tid >> 2;            // 0..63 (row within tile)
    int lk = (tid & 3) * 4;       // k offset 0,4,8,12

    const float* Wp = g_Weff;     // [3072][1024]

    float acc[4][4];
#pragma unroll
    for (int i = 0; i < 4; i++)
#pragma unroll
        for (int j = 0; j < 4; j++) acc[i][j] = 0.f;

    for (int k0 = 0; k0 < HID; k0 += GBK) {
        float4 av = *(const float4*)&X[(size_t)(m0 + lm) * HID + k0 + lk];
        float4 bv4 = *(const float4*)&Wp[(size_t)(c0 + lm) * HID + k0 + lk];
        __syncthreads();
        As[(lk + 0) * 68 + lm] = av.x;
        As[(lk + 1) * 68 + lm] = av.y;
        As[(lk + 2) * 68 + lm] = av.z;
        As[(lk + 3) * 68 + lm] = av.w;
        Bs[(lk + 0) * 68 + lm] = bv4.x;
        Bs[(lk + 1) * 68 + lm] = bv4.y;
        Bs[(lk + 2) * 68 + lm] = bv4.z;
        Bs[(lk + 3) * 68 + lm] = bv4.w;
        __syncthreads();
#pragma unroll
        for (int k = 0; k < GBK; k++) {
            float4 a = *(const float4*)&As[k * 68 + ty * 4];
            float4 b = *(const float4*)&Bs[k * 68 + tx * 4];
            float ar[4] = {a.x, a.y, a.z, a.w};
            float br[4] = {b.x, b.y, b.z, b.w};
#pragma unroll
            for (int i = 0; i < 4; i++)
#pragma unroll
                for (int j = 0; j < 4; j++)
                    acc[i][j] += ar[i] * br[j];
        }
    }

    // epilogue: bias + scatter into [mat][b][h][t][d]
#pragma unroll
    for (int j = 0; j < 4; j++) {
        int c = c0 + tx * 4 + j;
        int mat = c >> 10;
        int o = c & 1023;
        const float* bias = (mat == 0) ? bq : (mat == 1) ? bk : bv;
        float bval = bias[o];
        int h = o >> 6;
        int d = o & 63;
#pragma unroll
        for (int i = 0; i < 4; i++) {
            int m = m0 + ty * 4 + i;
            int b = m >> 11;
            int t = m & 2047;
            g_QKV[((size_t)((mat * BB + b) * NH + h) * TT + t) * HD + d] = acc[i][j] + bval;
        }
    }
}

// ---------------------------------------------------------------------------
// Kernel 3: causal flash attention (fp32).
// One block = (b, h, q-tile of 64). 256 threads: quad (4 threads) per q row.
// Online softmax; K/V tiles 64x64 in smem; P staged in smem per warp.
// ---------------------------------------------------------------------------
#define ST 68   // smem row stride (floats); 68 => conflict-free LDS.128 patterns
__global__ void attn_kernel(const float* __restrict__ mask, float* __restrict__ out) {
    extern __shared__ float sm[];
    float* Qs = sm;                 // 64*ST
    float* Ks = sm + 64 * ST;
    float* Vs = sm + 2 * 64 * ST;
    float* Ps = sm + 3 * 64 * ST;

    int qt = blockIdx.x;
    int h  = blockIdx.y;
    int b  = blockIdx.z;

    const float* Qg = g_QKV + (size_t)((0 * BB + b) * NH + h) * TT * HD;
    const float* Kg = g_QKV + (size_t)((1 * BB + b) * NH + h) * TT * HD;
    const float* Vg = g_QKV + (size_t)((2 * BB + b) * NH + h) * TT * HD;
    const float* maskb = mask + (size_t)b * TT;

    int tid = threadIdx.x;
    int row = tid >> 2;    // q row within tile (0..63)
    int tx  = tid & 3;     // quad lane
    int q   = qt * 64 + row;

    // load Q tile (float4, coalesced)
    for (int i = tid; i < 64 * 16; i += 256) {
        int r = i >> 4, d4 = i & 15;
        *(float4*)&Qs[r * ST + d4 * 4] = *(const float4*)&Qg[(size_t)(qt * 64 + r) * HD + d4 * 4];
    }

    float4 o0 = make_float4(0.f, 0.f, 0.f, 0.f), o1 = o0, o2 = o0, o3 = o0;
    float mrun = -INFINITY, lrun = 0.f;

    for (int kt = 0; kt <= qt; kt++) {
        __syncthreads();
        for (int i = tid; i < 64 * 16; i += 256) {
            int r = i >> 4, d4 = i & 15;
            *(float4*)&Ks[r * ST + d4 * 4] = *(const float4*)&Kg[(size_t)(kt * 64 + r) * HD + d4 * 4];
            *(float4*)&Vs[r * ST + d4 * 4] = *(const float4*)&Vg[(size_t)(kt * 64 + r) * HD + d4 * 4];
        }
        __syncthreads();

        // scores: this thread owns k = kk*4 + tx, kk in [0,16)
        float s[16];
#pragma unroll
        for (int kk = 0; kk < 16; kk++) s[kk] = 0.f;
#pragma unroll
        for (int d4 = 0; d4 < 16; d4++) {
            float4 qv = *(const float4*)&Qs[row * ST + d4 * 4];
#pragma unroll
            for (int kk = 0; kk < 16; kk++) {
                float4 kv = *(const float4*)&Ks[(kk * 4 + tx) * ST + d4 * 4];
                s[kk] += qv.x * kv.x + qv.y * kv.y + qv.z * kv.z + qv.w * kv.w;
            }
        }

        // scale + mask + causal, local max
        float tm = -INFINITY;
#pragma unroll
        for (int kk = 0; kk < 16; kk++) {
            int kg = kt * 64 + kk * 4 + tx;
            float sv = s[kk] * 0.125f + maskb[kg];
            if (kg > q) sv = -INFINITY;
            s[kk] = sv;
            tm = fmaxf(tm, sv);
        }
        tm = fmaxf(tm, __shfl_xor_sync(0xffffffffu, tm, 1));
        tm = fmaxf(tm, __shfl_xor_sync(0xffffffffu, tm, 2));

        float mn = fmaxf(mrun, tm);
        float corr = __expf(mrun - mn);
        float ls = 0.f;
#pragma unroll
        for (int kk = 0; kk < 16; kk++) {
            float p = __expf(s[kk] - mn);
            s[kk] = p;
            ls += p;
        }
        ls += __shfl_xor_sync(0xffffffffu, ls, 1);
        ls += __shfl_xor_sync(0xffffffffu, ls, 2);
        lrun = lrun * corr + ls;
        mrun = mn;

        o0.x *= corr; o0.y *= corr; o0.z *= corr; o0.w *= corr;
        o1.x *= corr; o1.y *= corr; o1.z *= corr; o1.w *= corr;
        o2.x *= corr; o2.y *= corr; o2.z *= corr; o2.w *= corr;
        o3.x *= corr; o3.y *= corr; o3.z *= corr; o3.w *= corr;

        // stage P (warp-private rows)
#pragma unroll
        for (int kk = 0; kk < 16; kk++) Ps[row * ST + kk * 4 + tx] = s[kk];
        __syncwarp();

        // O += P @ V ; this thread owns dims d = jj*16 + tx*4 + {0..3}
#pragma unroll 4
        for (int k = 0; k < 64; k++) {
            float p = Ps[row * ST + k];
            float4 v0 = *(const float4*)&Vs[k * ST +  0 + tx * 4];
            float4 v1 = *(const float4*)&Vs[k * ST + 16 + tx * 4];
            float4 v2 = *(const float4*)&Vs[k * ST + 32 + tx * 4];
            float4 v3 = *(const float4*)&Vs[k * ST + 48 + tx * 4];
            o0.x += p * v0.x; o0.y += p * v0.y; o0.z += p * v0.z; o0.w += p * v0.w;
            o1.x += p * v1.x; o1.y += p * v1.y; o1.z += p * v1.z; o1.w += p * v1.w;
            o2.x += p * v2.x; o2.y += p * v2.y; o2.z += p * v2.z; o2.w += p * v2.w;
            o3.x += p * v3.x; o3.y += p * v3.y; o3.z += p * v3.z; o3.w += p * v3.w;
        }
        __syncwarp();
    }

    float inv = 1.f / lrun;
    float* op = out + ((size_t)(b * TT + q)) * (NH * HD) + h * HD;
    op[ 0 + tx * 4 + 0] = o0.x * inv; op[ 0 + tx * 4 + 1] = o0.y * inv;
    op[ 0 + tx * 4 + 2] = o0.z * inv; op[ 0 + tx * 4 + 3] = o0.w * inv;
    op[16 + tx * 4 + 0] = o1.x * inv; op[16 + tx * 4 + 1] = o1.y * inv;
    op[16 + tx * 4 + 2] = o1.z * inv; op[16 + tx * 4 + 3] = o1.w * inv;
    op[32 + tx * 4 + 0] = o2.x * inv; op[32 + tx * 4 + 1] = o2.y * inv;
    op[32 + tx * 4 + 2] = o2.z * inv; op[32 + tx * 4 + 3] = o2.w * inv;
    op[48 + tx * 4 + 0] = o3.x * inv; op[48 + tx * 4 + 1] = o3.y * inv;
    op[48 + tx * 4 + 2] = o3.z * inv; op[48 + tx * 4 + 3] = o3.w * inv;
}

// ---------------------------------------------------------------------------
extern "C" void kernel_launch(void* const* d_in, const int* in_sizes, int n_in,
                              void* d_out, int out_size) {
    const float* X    = (const float*)d_in[0];
    const float* mask = (const float*)d_in[1];
    const float* Wq = (const float*)d_in[2];
    const float* bq = (const float*)d_in[3];
    const float* Aq = (const float*)d_in[4];
    const float* Bq = (const float*)d_in[5];
    const float* Wk = (const float*)d_in[6];
    const float* bk = (const float*)d_in[7];
    const float* Ak = (const float*)d_in[8];
    const float* Bk = (const float*)d_in[9];
    const float* Wv = (const float*)d_in[10];
    const float* bv = (const float*)d_in[11];
    const float* Av = (const float*)d_in[12];
    const float* Bv = (const float*)d_in[13];
    float* out = (float*)d_out;

    // 1) fold LoRA into dense weights
    fold_lora_kernel<<<(3 * HID * HID + 255) / 256, 256>>>(Wq, Aq, Bq, Wk, Ak, Bk, Wv, Av, Bv);

    // 2) fused QKV projection
    qkv_gemm_kernel<<<dim3(3 * HID / 64, BB * TT / 64), 256>>>(X, bq, bk, bv);

    // 3) causal flash attention
    static int smem_set = 0;
    size_t smem = 4 * 64 * ST * sizeof(float);  // 69632 B
    cudaFuncSetAttribute(attn_kernel, cudaFuncAttributeMaxDynamicSharedMemorySize, (int)smem);
    attn_kernel<<<dim3(TT / 64, NH, BB), 256, smem>>>(mask, out);
    (void)smem_set; (void)in_sizes; (void)n_in; (void)out_size;
}

// round 5
// speedup vs baseline: 3.6557x; 3.6557x over previous
#include <cuda_runtime.h>
#include <cuda_bf16.h>
#include <math.h>
#include <cstdint>

// Problem constants
#define HID 1024
#define NH  16
#define HD  64
#define BB  4
#define TT  2048
#define RR  8
#define SCALING 2.0f

// Scratch (device globals; no allocation allowed)
__device__ float g_Weff[3 * HID * HID];        // [3072][1024] row-major (K contiguous)
__device__ float g_QKV[3 * BB * NH * TT * HD]; // [mat][b][h][t][d]

// ---------------------------------------------------------------------------
// helpers
// ---------------------------------------------------------------------------
__device__ __forceinline__ uint32_t smem_u32(const void* p) {
    uint32_t a;
    asm("{ .reg .u64 t; cvta.to.shared.u64 t, %1; cvt.u32.u64 %0, t; }" : "=r"(a) : "l"(p));
    return a;
}
__device__ __forceinline__ uint32_t f2tf32(float x) {
    uint32_t r;
    asm("cvt.rna.tf32.f32 %0, %1;" : "=r"(r) : "f"(x));
    return r;
}
__device__ __forceinline__ void mma_tf32(float c[4], uint32_t a0, uint32_t a1, uint32_t a2, uint32_t a3,
                                         uint32_t b0, uint32_t b1) {
    asm volatile(
        "mma.sync.aligned.m16n8k8.row.col.f32.tf32.tf32.f32 "
        "{%0,%1,%2,%3},{%4,%5,%6,%7},{%8,%9},{%0,%1,%2,%3};"
        : "+f"(c[0]), "+f"(c[1]), "+f"(c[2]), "+f"(c[3])
        : "r"(a0), "r"(a1), "r"(a2), "r"(a3), "r"(b0), "r"(b1));
}
__device__ __forceinline__ void cp_async16(uint32_t smem, const void* gmem) {
    asm volatile("cp.async.cg.shared.global [%0], [%1], 16;" :: "r"(smem), "l"(gmem));
}
#define CP_COMMIT() asm volatile("cp.async.commit_group;" ::: "memory")
template <int N> __device__ __forceinline__ void cp_wait() {
    asm volatile("cp.async.wait_group %0;" :: "n"(N) : "memory");
}

// ---------------------------------------------------------------------------
// Kernel 1: fold LoRA into dense weights
// ---------------------------------------------------------------------------
__global__ void fold_lora_kernel(const float* __restrict__ W0, const float* __restrict__ A0, const float* __restrict__ B0,
                                 const float* __restrict__ W1, const float* __restrict__ A1, const float* __restrict__ B1,
                                 const float* __restrict__ W2, const float* __restrict__ A2, const float* __restrict__ B2) {
    int idx = blockIdx.x * blockDim.x + threadIdx.x;
    if (idx >= 3 * HID * HID) return;
    int mat = idx >> 20;
    int oi  = idx & (HID * HID - 1);
    int o   = oi >> 10;
    int i   = oi & 1023;
    const float* W = (mat == 0) ? W0 : (mat == 1) ? W1 : W2;
    const float* A = (mat == 0) ? A0 : (mat == 1) ? A1 : A2;
    const float* Bm = (mat == 0) ? B0 : (mat == 1) ? B1 : B2;
    float acc = W[oi];
#pragma unroll
    for (int r = 0; r < RR; r++)
        acc += SCALING * Bm[o * RR + r] * A[r * HID + i];
    g_Weff[idx] = acc;
}

// ---------------------------------------------------------------------------
// Kernel 2: QKV GEMM via mma.sync tf32.
// D[m,c] = sum_k X[m,k]*Weff[c,k] + bias.  BM=BN=128, BK=32, 3-stage cp.async.
// 8 warps in 2(M)x4(N); warp tile 64x32; mma m16n8k8.
// ---------------------------------------------------------------------------
#define BKG 32
#define GSTAGES 3
#define APAD 36
#define STG_FLOATS (2 * 128 * APAD)          // A + B per stage
#define GEMM_SMEM (GSTAGES * STG_FLOATS * 4) // bytes

__global__ void __launch_bounds__(256)
qkv_gemm_mma(const float* __restrict__ X,
             const float* __restrict__ bq, const float* __restrict__ bk, const float* __restrict__ bv) {
    extern __shared__ float smf[];
    uint32_t sbase = smem_u32(smf);

    int tid = threadIdx.x;
    int w    = tid >> 5;
    int lane = tid & 31;
    int gid  = lane >> 2;
    int tid4 = lane & 3;
    int wm = w & 1;       // 0..1  (64 rows each)
    int wn = w >> 1;      // 0..3  (32 cols each)

    int m0b = blockIdx.y * 128;
    int n0b = blockIdx.x * 128;
    const float* Wp = g_Weff;

    auto load_stage = [&](int kt, int slot) {
        int k0 = kt * BKG;
        uint32_t sa = sbase + (uint32_t)(slot * STG_FLOATS) * 4;
        uint32_t sb = sa + 128 * APAD * 4;
#pragma unroll
        for (int i = 0; i < 4; i++) {
            int ch = tid + i * 256;           // 0..1023
            int row = ch >> 3, c4 = ch & 7;
            uint32_t off = (uint32_t)(row * APAD + c4 * 4) * 4;
            cp_async16(sa + off, X  + (size_t)(m0b + row) * HID + k0 + c4 * 4);
            cp_async16(sb + off, Wp + (size_t)(n0b + row) * HID + k0 + c4 * 4);
        }
        CP_COMMIT();
    };

    float acc[4][4][4];
#pragma unroll
    for (int mm = 0; mm < 4; mm++)
#pragma unroll
        for (int nn = 0; nn < 4; nn++)
#pragma unroll
            for (int j = 0; j < 4; j++) acc[mm][nn][j] = 0.f;

    load_stage(0, 0);
    load_stage(1, 1);

    const int NKT = HID / BKG;   // 32
    for (int kt = 0; kt < NKT; kt++) {
        int slot = kt % GSTAGES;
        if (kt >= NKT - 2) cp_wait<0>(); else cp_wait<1>();
        __syncthreads();
        if (kt + 2 < NKT) load_stage(kt + 2, (kt + 2) % GSTAGES);

        const float* As = smf + slot * STG_FLOATS + (wm * 64) * APAD;
        const float* Bs = smf + slot * STG_FLOATS + 128 * APAD + (wn * 32) * APAD;
#pragma unroll
        for (int ks = 0; ks < 4; ks++) {
            int kc = ks * 8;
            uint32_t af[4][4];
#pragma unroll
            for (int mm = 0; mm < 4; mm++) {
                const float* ar = As + (mm * 16 + gid) * APAD + kc;
                af[mm][0] = f2tf32(ar[tid4]);
                af[mm][1] = f2tf32(ar[8 * APAD + tid4]);
                af[mm][2] = f2tf32(ar[tid4 + 4]);
                af[mm][3] = f2tf32(ar[8 * APAD + tid4 + 4]);
            }
            uint32_t bf[4][2];
#pragma unroll
            for (int nn = 0; nn < 4; nn++) {
                const float* br = Bs + (nn * 8 + gid) * APAD + kc;
                bf[nn][0] = f2tf32(br[tid4]);
                bf[nn][1] = f2tf32(br[tid4 + 4]);
            }
#pragma unroll
            for (int mm = 0; mm < 4; mm++)
#pragma unroll
                for (int nn = 0; nn < 4; nn++)
                    mma_tf32(acc[mm][nn], af[mm][0], af[mm][1], af[mm][2], af[mm][3], bf[nn][0], bf[nn][1]);
        }
    }

    // epilogue: bias + scatter to g_QKV[mat][b][h][t][d]
#pragma unroll
    for (int nn = 0; nn < 4; nn++) {
        int c = n0b + wn * 32 + nn * 8 + tid4 * 2;
        int mat = c >> 10;
        int o = c & 1023;
        const float* bias = (mat == 0) ? bq : (mat == 1) ? bk : bv;
        float b0v = bias[o], b1v = bias[o + 1];
        int h = o >> 6, d = o & 63;
#pragma unroll
        for (int mm = 0; mm < 4; mm++) {
            int m = m0b + wm * 64 + mm * 16 + gid;
            int bi = m >> 11, t = m & 2047;
            float* dst = g_QKV + ((size_t)((mat * BB + bi) * NH + h) * TT + t) * HD + d;
            *(float2*)dst = make_float2(acc[mm][nn][0] + b0v, acc[mm][nn][1] + b1v);
            int m2 = m + 8;
            int bi2 = m2 >> 11, t2 = m2 & 2047;
            float* dst2 = g_QKV + ((size_t)((mat * BB + bi2) * NH + h) * TT + t2) * HD + d;
            *(float2*)dst2 = make_float2(acc[mm][nn][2] + b0v, acc[mm][nn][3] + b1v);
        }
    }
}

// ---------------------------------------------------------------------------
// Kernel 3: causal flash attention, tf32 mma for QK^T and PV, smem-staged S/P.
// Block = 64 q-rows. 256 threads = 8 warps in 4(M)x2(N).
// ---------------------------------------------------------------------------
#define ST 68
#define ATTN_SMEM ((4 * 64 * ST + 3 * 64) * 4)

__global__ void __launch_bounds__(256)
attn_mma(const float* __restrict__ mask, float* __restrict__ out) {
    extern __shared__ float sm[];
    float* Qs = sm;
    float* Ks = sm + 64 * ST;
    float* Vs = sm + 2 * 64 * ST;
    float* Ss = sm + 3 * 64 * ST;
    float* sm_m = sm + 4 * 64 * ST;
    float* sm_l = sm_m + 64;
    float* sm_c = sm_m + 128;

    int qt = gridDim.x - 1 - blockIdx.x;   // heavy blocks first
    int h  = blockIdx.y;
    int b  = blockIdx.z;

    const float* Qg = g_QKV + (size_t)((0 * BB + b) * NH + h) * TT * HD;
    const float* Kg = g_QKV + (size_t)((1 * BB + b) * NH + h) * TT * HD;
    const float* Vg = g_QKV + (size_t)((2 * BB + b) * NH + h) * TT * HD;
    const float* maskb = mask + (size_t)b * TT;

    int tid = threadIdx.x;
    int w    = tid >> 5;
    int lane = tid & 31;
    int gid  = lane >> 2;
    int tid4 = lane & 3;
    int wm = w & 3;      // 0..3 : 16 q-rows each
    int wn = w >> 2;     // 0..1 : 32 cols each
    int rowb = wm * 16;
    int colb = wn * 32;

    // load Q tile pre-scaled by 1/sqrt(D)
    for (int i = tid; i < 64 * 16; i += 256) {
        int r = i >> 4, d4 = i & 15;
        float4 v = *(const float4*)&Qg[(size_t)(qt * 64 + r) * HD + d4 * 4];
        v.x *= 0.125f; v.y *= 0.125f; v.z *= 0.125f; v.w *= 0.125f;
        *(float4*)&Qs[r * ST + d4 * 4] = v;
    }
    if (tid < 64) { sm_m[tid] = -INFINITY; sm_l[tid] = 0.f; }

    float cO[4][4];
#pragma unroll
    for (int nn = 0; nn < 4; nn++)
#pragma unroll
        for (int j = 0; j < 4; j++) cO[nn][j] = 0.f;

    // softmax thread mapping: quad per row
    int srow = tid >> 2;
    int stx  = tid & 3;

    for (int kt = 0; kt <= qt; kt++) {
        __syncthreads();  // prev PV done with Ss/Vs; prev loads done with Ks
        for (int i = tid; i < 64 * 16; i += 256) {
            int r = i >> 4, d4 = i & 15;
            *(float4*)&Ks[r * ST + d4 * 4] = *(const float4*)&Kg[(size_t)(kt * 64 + r) * HD + d4 * 4];
            *(float4*)&Vs[r * ST + d4 * 4] = *(const float4*)&Vg[(size_t)(kt * 64 + r) * HD + d4 * 4];
        }
        __syncthreads();

        // ---- S = Q @ K^T (scaled) ----
        float cS[4][4];
#pragma unroll
        for (int nn = 0; nn < 4; nn++)
#pragma unroll
            for (int j = 0; j < 4; j++) cS[nn][j] = 0.f;
#pragma unroll
        for (int ks = 0; ks < 8; ks++) {
            int kc = ks * 8;
            const float* qr = Qs + (rowb + gid) * ST + kc;
            uint32_t a0 = f2tf32(qr[tid4]);
            uint32_t a1 = f2tf32(qr[8 * ST + tid4]);
            uint32_t a2 = f2tf32(qr[tid4 + 4]);
            uint32_t a3 = f2tf32(qr[8 * ST + tid4 + 4]);
#pragma unroll
            for (int nn = 0; nn < 4; nn++) {
                const float* kr = Ks + (colb + nn * 8 + gid) * ST + kc;
                uint32_t b0 = f2tf32(kr[tid4]);
                uint32_t b1 = f2tf32(kr[tid4 + 4]);
                mma_tf32(cS[nn], a0, a1, a2, a3, b0, b1);
            }
        }
#pragma unroll
        for (int nn = 0; nn < 4; nn++) {
            int cc = colb + nn * 8 + tid4 * 2;
            *(float2*)&Ss[(rowb + gid) * ST + cc]     = make_float2(cS[nn][0], cS[nn][1]);
            *(float2*)&Ss[(rowb + gid + 8) * ST + cc] = make_float2(cS[nn][2], cS[nn][3]);
        }
        __syncthreads();

        // ---- softmax on Ss rows (quad per row, 16 contiguous cols each) ----
        {
            float s[16];
            const float* srp = Ss + srow * ST + stx * 16;
#pragma unroll
            for (int jj = 0; jj < 4; jj++) {
                float4 v = *(const float4*)&srp[jj * 4];
                s[jj * 4 + 0] = v.x; s[jj * 4 + 1] = v.y; s[jj * 4 + 2] = v.z; s[jj * 4 + 3] = v.w;
            }
            int kgb = kt * 64 + stx * 16;
#pragma unroll
            for (int jj = 0; jj < 4; jj++) {
                float4 mv = *(const float4*)&maskb[kgb + jj * 4];
                s[jj * 4 + 0] += mv.x; s[jj * 4 + 1] += mv.y; s[jj * 4 + 2] += mv.z; s[jj * 4 + 3] += mv.w;
            }
            if (kt == qt) {
                int q = qt * 64 + srow;
#pragma unroll
                for (int j = 0; j < 16; j++)
                    if (kgb + j > q) s[j] = -INFINITY;
            }
            float tm = -INFINITY;
#pragma unroll
            for (int j = 0; j < 16; j++) tm = fmaxf(tm, s[j]);
            tm = fmaxf(tm, __shfl_xor_sync(0xffffffffu, tm, 1));
            tm = fmaxf(tm, __shfl_xor_sync(0xffffffffu, tm, 2));
            float m_old = sm_m[srow];
            float mn = fmaxf(m_old, tm);
            float corr = __expf(m_old - mn);
            float ls = 0.f;
#pragma unroll
            for (int j = 0; j < 16; j++) { s[j] = __expf(s[j] - mn); ls += s[j]; }
            ls += __shfl_xor_sync(0xffffffffu, ls, 1);
            ls += __shfl_xor_sync(0xffffffffu, ls, 2);
            float* swp = Ss + srow * ST + stx * 16;
#pragma unroll
            for (int jj = 0; jj < 4; jj++)
                *(float4*)&swp[jj * 4] = make_float4(s[jj * 4 + 0], s[jj * 4 + 1], s[jj * 4 + 2], s[jj * 4 + 3]);
            if (stx == 0) {
                sm_m[srow] = mn;
                sm_l[srow] = sm_l[srow] * corr + ls;
                sm_c[srow] = corr;
            }
        }
        __syncthreads();

        // ---- O = O*corr + P @ V ----
        float corr0 = sm_c[rowb + gid];
        float corr1 = sm_c[rowb + gid + 8];
#pragma unroll
        for (int nn = 0; nn < 4; nn++) {
            cO[nn][0] *= corr0; cO[nn][1] *= corr0;
            cO[nn][2] *= corr1; cO[nn][3] *= corr1;
        }
#pragma unroll
        for (int ks = 0; ks < 8; ks++) {
            int kc = ks * 8;
            const float* pr = Ss + (rowb + gid) * ST + kc;
            uint32_t a0 = f2tf32(pr[tid4]);
            uint32_t a1 = f2tf32(pr[8 * ST + tid4]);
            uint32_t a2 = f2tf32(pr[tid4 + 4]);
            uint32_t a3 = f2tf32(pr[8 * ST + tid4 + 4]);
#pragma unroll
            for (int nn = 0; nn < 4; nn++) {
                const float* vr = Vs + (kc + tid4) * ST + colb + nn * 8 + gid;
                uint32_t b0 = f2tf32(vr[0]);
                uint32_t b1 = f2tf32(vr[4 * ST]);
                mma_tf32(cO[nn], a0, a1, a2, a3, b0, b1);
            }
        }
    }

    __syncthreads();
    float inv0 = 1.f / sm_l[rowb + gid];
    float inv1 = 1.f / sm_l[rowb + gid + 8];
    int q0 = qt * 64 + rowb + gid;
#pragma unroll
    for (int nn = 0; nn < 4; nn++) {
        int d = colb + nn * 8 + tid4 * 2;
        float* o0p = out + ((size_t)(b * TT + q0)) * (NH * HD) + h * HD + d;
        *(float2*)o0p = make_float2(cO[nn][0] * inv0, cO[nn][1] * inv0);
        float* o1p = out + ((size_t)(b * TT + q0 + 8)) * (NH * HD) + h * HD + d;
        *(float2*)o1p = make_float2(cO[nn][2] * inv1, cO[nn][3] * inv1);
    }
}

// ---------------------------------------------------------------------------
extern "C" void kernel_launch(void* const* d_in, const int* in_sizes, int n_in,
                              void* d_out, int out_size) {
    const float* X    = (const float*)d_in[0];
    const float* mask = (const float*)d_in[1];
    const float* Wq = (const float*)d_in[2];
    const float* bq = (const float*)d_in[3];
    const float* Aq = (const float*)d_in[4];
    const float* Bq = (const float*)d_in[5];
    const float* Wk = (const float*)d_in[6];
    const float* bk = (const float*)d_in[7];
    const float* Ak = (const float*)d_in[8];
    const float* Bk = (const float*)d_in[9];
    const float* Wv = (const float*)d_in[10];
    const float* bv = (const float*)d_in[11];
    const float* Av = (const float*)d_in[12];
    const float* Bv = (const float*)d_in[13];
    float* out = (float*)d_out;

    // 1) fold LoRA into dense weights
    fold_lora_kernel<<<(3 * HID * HID + 255) / 256, 256>>>(Wq, Aq, Bq, Wk, Ak, Bk, Wv, Av, Bv);

    // 2) fused QKV projection on tensor cores (tf32 mma.sync)
    cudaFuncSetAttribute(qkv_gemm_mma, cudaFuncAttributeMaxDynamicSharedMemorySize, GEMM_SMEM);
    qkv_gemm_mma<<<dim3(3 * HID / 128, BB * TT / 128), 256, GEMM_SMEM>>>(X, bq, bk, bv);

    // 3) causal flash attention (tf32 mma.sync)
    cudaFuncSetAttribute(attn_mma, cudaFuncAttributeMaxDynamicSharedMemorySize, ATTN_SMEM);
    attn_mma<<<dim3(TT / 64, NH, BB), 256, ATTN_SMEM>>>(mask, out);
    (void)in_sizes; (void)n_in; (void)out_size;
}

// round 6
// speedup vs baseline: 4.3341x; 1.1856x over previous
#include <cuda_runtime.h>
#include <cuda_bf16.h>
#include <math.h>
#include <cstdint>

// Problem constants
#define HID 1024
#define NH  16
#define HD  64
#define BB  4
#define TT  2048
#define RR  8
#define SCALING 2.0f

// Scratch (device globals; no allocation allowed)
__device__ float g_Weff[3 * HID * HID];        // tf32-truncated bits
__device__ float g_Xt[BB * TT * HID];          // tf32-truncated X
__device__ float g_QKV[3 * BB * NH * TT * HD]; // [mat][b][h][t][d]; tf32 bits, Q pre-scaled

// ---------------------------------------------------------------------------
// helpers
// ---------------------------------------------------------------------------
__device__ __forceinline__ uint32_t smem_u32(const void* p) {
    uint32_t a;
    asm("{ .reg .u64 t; cvta.to.shared.u64 t, %1; cvt.u32.u64 %0, t; }" : "=r"(a) : "l"(p));
    return a;
}
__device__ __forceinline__ uint32_t f2tf32(float x) {
    uint32_t r;
    asm("cvt.rna.tf32.f32 %0, %1;" : "=r"(r) : "f"(x));
    return r;
}
__device__ __forceinline__ void mma_tf32(float c[4], uint32_t a0, uint32_t a1, uint32_t a2, uint32_t a3,
                                         uint32_t b0, uint32_t b1) {
    asm volatile(
        "mma.sync.aligned.m16n8k8.row.col.f32.tf32.tf32.f32 "
        "{%0,%1,%2,%3},{%4,%5,%6,%7},{%8,%9},{%0,%1,%2,%3};"
        : "+f"(c[0]), "+f"(c[1]), "+f"(c[2]), "+f"(c[3])
        : "r"(a0), "r"(a1), "r"(a2), "r"(a3), "r"(b0), "r"(b1));
}
__device__ __forceinline__ void cp_async16(uint32_t smem, const void* gmem) {
    asm volatile("cp.async.cg.shared.global [%0], [%1], 16;" :: "r"(smem), "l"(gmem));
}
#define CP_COMMIT() asm volatile("cp.async.commit_group;" ::: "memory")
template <int N> __device__ __forceinline__ void cp_wait() {
    asm volatile("cp.async.wait_group %0;" :: "n"(N) : "memory");
}

// ---------------------------------------------------------------------------
// Kernel 1a: fold LoRA into dense weights (tf32-truncated output)
// ---------------------------------------------------------------------------
__global__ void fold_lora_kernel(const float* __restrict__ W0, const float* __restrict__ A0, const float* __restrict__ B0,
                                 const float* __restrict__ W1, const float* __restrict__ A1, const float* __restrict__ B1,
                                 const float* __restrict__ W2, const float* __restrict__ A2, const float* __restrict__ B2) {
    int idx = blockIdx.x * blockDim.x + threadIdx.x;
    if (idx >= 3 * HID * HID) return;
    int mat = idx >> 20;
    int oi  = idx & (HID * HID - 1);
    int o   = oi >> 10;
    int i   = oi & 1023;
    const float* W = (mat == 0) ? W0 : (mat == 1) ? W1 : W2;
    const float* A = (mat == 0) ? A0 : (mat == 1) ? A1 : A2;
    const float* Bm = (mat == 0) ? B0 : (mat == 1) ? B1 : B2;
    float acc = W[oi];
#pragma unroll
    for (int r = 0; r < RR; r++)
        acc += SCALING * Bm[o * RR + r] * A[r * HID + i];
    g_Weff[idx] = __uint_as_float(f2tf32(acc));
}

// ---------------------------------------------------------------------------
// Kernel 1b: truncate X to tf32 bits
// ---------------------------------------------------------------------------
__global__ void trunc_x_kernel(const float* __restrict__ X) {
    int i = blockIdx.x * blockDim.x + threadIdx.x;   // float4 index
    if (i >= BB * TT * HID / 4) return;
    float4 v = ((const float4*)X)[i];
    v.x = __uint_as_float(f2tf32(v.x));
    v.y = __uint_as_float(f2tf32(v.y));
    v.z = __uint_as_float(f2tf32(v.z));
    v.w = __uint_as_float(f2tf32(v.w));
    ((float4*)g_Xt)[i] = v;
}

// ---------------------------------------------------------------------------
// Kernel 2: QKV GEMM via mma.sync tf32 (inputs pre-truncated -> no CVT in loop).
// ---------------------------------------------------------------------------
#define BKG 32
#define GSTAGES 3
#define APAD 36
#define STG_FLOATS (2 * 128 * APAD)
#define GEMM_SMEM (GSTAGES * STG_FLOATS * 4)

__global__ void __launch_bounds__(256)
qkv_gemm_mma(const float* __restrict__ bq, const float* __restrict__ bk, const float* __restrict__ bv) {
    extern __shared__ float smf[];
    uint32_t sbase = smem_u32(smf);

    int tid = threadIdx.x;
    int w    = tid >> 5;
    int lane = tid & 31;
    int gid  = lane >> 2;
    int tid4 = lane & 3;
    int wm = w & 1;
    int wn = w >> 1;

    int m0b = blockIdx.y * 128;
    int n0b = blockIdx.x * 128;
    const float* Wp = g_Weff;
    const float* Xp = g_Xt;

    auto load_stage = [&](int kt, int slot) {
        int k0 = kt * BKG;
        uint32_t sa = sbase + (uint32_t)(slot * STG_FLOATS) * 4;
        uint32_t sb = sa + 128 * APAD * 4;
#pragma unroll
        for (int i = 0; i < 4; i++) {
            int ch = tid + i * 256;
            int row = ch >> 3, c4 = ch & 7;
            uint32_t off = (uint32_t)(row * APAD + c4 * 4) * 4;
            cp_async16(sa + off, Xp + (size_t)(m0b + row) * HID + k0 + c4 * 4);
            cp_async16(sb + off, Wp + (size_t)(n0b + row) * HID + k0 + c4 * 4);
        }
        CP_COMMIT();
    };

    float acc[4][4][4];
#pragma unroll
    for (int mm = 0; mm < 4; mm++)
#pragma unroll
        for (int nn = 0; nn < 4; nn++)
#pragma unroll
            for (int j = 0; j < 4; j++) acc[mm][nn][j] = 0.f;

    load_stage(0, 0);
    load_stage(1, 1);

    const int NKT = HID / BKG;
    for (int kt = 0; kt < NKT; kt++) {
        int slot = kt % GSTAGES;
        if (kt >= NKT - 2) cp_wait<0>(); else cp_wait<1>();
        __syncthreads();
        if (kt + 2 < NKT) load_stage(kt + 2, (kt + 2) % GSTAGES);

        const uint32_t* As = (const uint32_t*)smf + slot * STG_FLOATS + (wm * 64) * APAD;
        const uint32_t* Bs = (const uint32_t*)smf + slot * STG_FLOATS + 128 * APAD + (wn * 32) * APAD;
#pragma unroll
        for (int ks = 0; ks < 4; ks++) {
            int kc = ks * 8;
            uint32_t af[4][4];
#pragma unroll
            for (int mm = 0; mm < 4; mm++) {
                const uint32_t* ar = As + (mm * 16 + gid) * APAD + kc;
                af[mm][0] = ar[tid4];
                af[mm][1] = ar[8 * APAD + tid4];
                af[mm][2] = ar[tid4 + 4];
                af[mm][3] = ar[8 * APAD + tid4 + 4];
            }
            uint32_t bf[4][2];
#pragma unroll
            for (int nn = 0; nn < 4; nn++) {
                const uint32_t* br = Bs + (nn * 8 + gid) * APAD + kc;
                bf[nn][0] = br[tid4];
                bf[nn][1] = br[tid4 + 4];
            }
#pragma unroll
            for (int mm = 0; mm < 4; mm++)
#pragma unroll
                for (int nn = 0; nn < 4; nn++)
                    mma_tf32(acc[mm][nn], af[mm][0], af[mm][1], af[mm][2], af[mm][3], bf[nn][0], bf[nn][1]);
        }
    }

    // epilogue: bias, Q pre-scale, truncate to tf32 bits, scatter
#pragma unroll
    for (int nn = 0; nn < 4; nn++) {
        int c = n0b + wn * 32 + nn * 8 + tid4 * 2;
        int mat = c >> 10;
        int o = c & 1023;
        const float* bias = (mat == 0) ? bq : (mat == 1) ? bk : bv;
        float b0v = bias[o], b1v = bias[o + 1];
        float scl = (mat == 0) ? 0.125f : 1.0f;
        int h = o >> 6, d = o & 63;
#pragma unroll
        for (int mm = 0; mm < 4; mm++) {
            int m = m0b + wm * 64 + mm * 16 + gid;
            int bi = m >> 11, t = m & 2047;
            float* dst = g_QKV + ((size_t)((mat * BB + bi) * NH + h) * TT + t) * HD + d;
            *(float2*)dst = make_float2(__uint_as_float(f2tf32((acc[mm][nn][0] + b0v) * scl)),
                                        __uint_as_float(f2tf32((acc[mm][nn][1] + b1v) * scl)));
            int m2 = m + 8;
            int bi2 = m2 >> 11, t2 = m2 & 2047;
            float* dst2 = g_QKV + ((size_t)((mat * BB + bi2) * NH + h) * TT + t2) * HD + d;
            *(float2*)dst2 = make_float2(__uint_as_float(f2tf32((acc[mm][nn][2] + b0v) * scl)),
                                         __uint_as_float(f2tf32((acc[mm][nn][3] + b1v) * scl)));
        }
    }
}

// ---------------------------------------------------------------------------
// Kernel 3: causal flash attention. Q-tile 128, K-tile 64.
// 8 warps, each owns 16 q-rows x ALL 64 cols -> warp-local softmax, 1 sync/tile.
// 3-stage cp.async K/V pipeline. All operands pre-truncated tf32 bits.
// ---------------------------------------------------------------------------
#define QR 128
#define KTL 64
#define STQ 68
#define STV 72
#define NSTG 3
#define OFF_Q  0
#define OFF_S  (QR * STQ)
#define OFF_K  (OFF_S + QR * STQ)
#define OFF_V  (OFF_K + NSTG * KTL * STQ)
#define ATTN_FLOATS (OFF_V + NSTG * KTL * STV)
#define ATTN_SMEM (ATTN_FLOATS * 4)

__global__ void __launch_bounds__(256)
attn_mma(const float* __restrict__ mask, float* __restrict__ out) {
    extern __shared__ float sm[];
    uint32_t sb = smem_u32(sm);

    int qt = gridDim.x - 1 - blockIdx.x;   // heavy blocks first
    int h  = blockIdx.y;
    int b  = blockIdx.z;

    const float* Qg = g_QKV + (size_t)((0 * BB + b) * NH + h) * TT * HD;
    const float* Kg = g_QKV + (size_t)((1 * BB + b) * NH + h) * TT * HD;
    const float* Vg = g_QKV + (size_t)((2 * BB + b) * NH + h) * TT * HD;
    const float* maskb = mask + (size_t)b * TT;

    int tid = threadIdx.x;
    int w    = tid >> 5;
    int lane = tid & 31;
    int gid  = lane >> 2;
    int tid4 = lane & 3;
    int rowb = w * 16;

    int nkt = 2 * (qt + 1);

    auto loadQ = [&]() {
#pragma unroll
        for (int i = 0; i < 8; i++) {
            int ch = tid + i * 256;
            int r = ch >> 4, c = ch & 15;
            cp_async16(sb + (uint32_t)(OFF_Q + r * STQ) * 4 + c * 16,
                       Qg + (size_t)(qt * QR + r) * HD + c * 4);
        }
    };
    auto loadKV = [&](int kt_) {
        int s = kt_ % NSTG;
#pragma unroll
        for (int i = 0; i < 4; i++) {
            int ch = tid + i * 256;
            int r = ch >> 4, c = ch & 15;
            cp_async16(sb + (uint32_t)(OFF_K + s * KTL * STQ + r * STQ) * 4 + c * 16,
                       Kg + (size_t)(kt_ * KTL + r) * HD + c * 4);
        }
#pragma unroll
        for (int i = 0; i < 4; i++) {
            int ch = tid + i * 256;
            int r = ch >> 4, c = ch & 15;
            cp_async16(sb + (uint32_t)(OFF_V + s * KTL * STV + r * STV) * 4 + c * 16,
                       Vg + (size_t)(kt_ * KTL + r) * HD + c * 4);
        }
    };

    loadQ(); loadKV(0); CP_COMMIT();
    if (nkt > 1) { loadKV(1); CP_COMMIT(); }

    float cO[8][4];
#pragma unroll
    for (int nn = 0; nn < 8; nn++)
#pragma unroll
        for (int j = 0; j < 4; j++) cO[nn][j] = 0.f;
    float m0 = -INFINITY, m1 = -INFINITY, l0 = 0.f, l1 = 0.f;

    const int q0 = qt * QR + rowb + gid;
    const int q1 = q0 + 8;

    for (int kt = 0; kt < nkt; kt++) {
        if (kt + 1 < nkt) cp_wait<1>(); else cp_wait<0>();
        __syncthreads();                       // visibility + all warps done with kt-1
        if (kt + 2 < nkt) { loadKV(kt + 2); CP_COMMIT(); }

        int stg = kt % NSTG;
        const uint32_t* Qs = (const uint32_t*)sm + OFF_Q;
        const uint32_t* Ks = (const uint32_t*)sm + OFF_K + stg * KTL * STQ;
        const uint32_t* Vs = (const uint32_t*)sm + OFF_V + stg * KTL * STV;
        uint32_t* Ps = (uint32_t*)sm + OFF_S;

        // ---- S = Q @ K^T ----
        float cS[8][4];
#pragma unroll
        for (int nn = 0; nn < 8; nn++)
#pragma unroll
            for (int j = 0; j < 4; j++) cS[nn][j] = 0.f;
#pragma unroll
        for (int ks = 0; ks < 8; ks++) {
            int kc = ks * 8;
            const uint32_t* qr = Qs + (rowb + gid) * STQ + kc;
            uint32_t a0 = qr[tid4];
            uint32_t a1 = qr[8 * STQ + tid4];
            uint32_t a2 = qr[tid4 + 4];
            uint32_t a3 = qr[8 * STQ + tid4 + 4];
#pragma unroll
            for (int nn = 0; nn < 8; nn++) {
                const uint32_t* kr = Ks + (nn * 8 + gid) * STQ + kc;
                mma_tf32(cS[nn], a0, a1, a2, a3, kr[tid4], kr[tid4 + 4]);
            }
        }

        // ---- mask + causal ----
        int colb0 = kt * KTL;
        bool diag = (kt >= 2 * qt);
#pragma unroll
        for (int nn = 0; nn < 8; nn++) {
            int c = colb0 + nn * 8 + 2 * tid4;
            float mk0 = __ldg(&maskb[c]);
            float mk1 = __ldg(&maskb[c + 1]);
            cS[nn][0] += mk0; cS[nn][1] += mk1;
            cS[nn][2] += mk0; cS[nn][3] += mk1;
            if (diag) {
                if (c     > q0) cS[nn][0] = -INFINITY;
                if (c + 1 > q0) cS[nn][1] = -INFINITY;
                if (c     > q1) cS[nn][2] = -INFINITY;
                if (c + 1 > q1) cS[nn][3] = -INFINITY;
            }
        }

        // ---- warp-local online softmax (quad reduction) ----
        float t0 = -INFINITY, t1 = -INFINITY;
#pragma unroll
        for (int nn = 0; nn < 8; nn++) {
            t0 = fmaxf(t0, fmaxf(cS[nn][0], cS[nn][1]));
            t1 = fmaxf(t1, fmaxf(cS[nn][2], cS[nn][3]));
        }
        t0 = fmaxf(t0, __shfl_xor_sync(0xffffffffu, t0, 1));
        t0 = fmaxf(t0, __shfl_xor_sync(0xffffffffu, t0, 2));
        t1 = fmaxf(t1, __shfl_xor_sync(0xffffffffu, t1, 1));
        t1 = fmaxf(t1, __shfl_xor_sync(0xffffffffu, t1, 2));
        float mn0 = fmaxf(m0, t0), mn1 = fmaxf(m1, t1);
        float cr0 = __expf(m0 - mn0), cr1 = __expf(m1 - mn1);
        m0 = mn0; m1 = mn1;
        float s0 = 0.f, s1 = 0.f;
#pragma unroll
        for (int nn = 0; nn < 8; nn++) {
            cS[nn][0] = __expf(cS[nn][0] - mn0); s0 += cS[nn][0];
            cS[nn][1] = __expf(cS[nn][1] - mn0); s0 += cS[nn][1];
            cS[nn][2] = __expf(cS[nn][2] - mn1); s1 += cS[nn][2];
            cS[nn][3] = __expf(cS[nn][3] - mn1); s1 += cS[nn][3];
        }
        s0 += __shfl_xor_sync(0xffffffffu, s0, 1);
        s0 += __shfl_xor_sync(0xffffffffu, s0, 2);
        s1 += __shfl_xor_sync(0xffffffffu, s1, 1);
        s1 += __shfl_xor_sync(0xffffffffu, s1, 2);
        l0 = l0 * cr0 + s0;
        l1 = l1 * cr1 + s1;
#pragma unroll
        for (int nn = 0; nn < 8; nn++) {
            cO[nn][0] *= cr0; cO[nn][1] *= cr0;
            cO[nn][2] *= cr1; cO[nn][3] *= cr1;
        }

        // ---- stage P (warp-private rows, tf32 bits) ----
#pragma unroll
        for (int nn = 0; nn < 8; nn++) {
            int cc = nn * 8 + 2 * tid4;
            *(uint2*)&Ps[(rowb + gid) * STQ + cc]     = make_uint2(f2tf32(cS[nn][0]), f2tf32(cS[nn][1]));
            *(uint2*)&Ps[(rowb + gid + 8) * STQ + cc] = make_uint2(f2tf32(cS[nn][2]), f2tf32(cS[nn][3]));
        }
        __syncwarp();

        // ---- O += P @ V ----
#pragma unroll
        for (int ks = 0; ks < 8; ks++) {
            int kc = ks * 8;
            const uint32_t* pr = Ps + (rowb + gid) * STQ + kc;
            uint32_t a0 = pr[tid4];
            uint32_t a1 = pr[8 * STQ + tid4];
            uint32_t a2 = pr[tid4 + 4];
            uint32_t a3 = pr[8 * STQ + tid4 + 4];
#pragma unroll
            for (int nn = 0; nn < 8; nn++) {
                const uint32_t* vr = Vs + (kc + tid4) * STV + nn * 8 + gid;
                mma_tf32(cO[nn], a0, a1, a2, a3, vr[0], vr[4 * STV]);
            }
        }
        __syncwarp();
    }

    // ---- output ----
    float inv0 = 1.f / l0;
    float inv1 = 1.f / l1;
#pragma unroll
    for (int nn = 0; nn < 8; nn++) {
        int d = nn * 8 + tid4 * 2;
        float* o0p = out + ((size_t)(b * TT + q0)) * (NH * HD) + h * HD + d;
        *(float2*)o0p = make_float2(cO[nn][0] * inv0, cO[nn][1] * inv0);
        float* o1p = out + ((size_t)(b * TT + q1)) * (NH * HD) + h * HD + d;
        *(float2*)o1p = make_float2(cO[nn][2] * inv1, cO[nn][3] * inv1);
    }
}

// ---------------------------------------------------------------------------
extern "C" void kernel_launch(void* const* d_in, const int* in_sizes, int n_in,
                              void* d_out, int out_size) {
    const float* X    = (const float*)d_in[0];
    const float* mask = (const float*)d_in[1];
    const float* Wq = (const float*)d_in[2];
    const float* bq = (const float*)d_in[3];
    const float* Aq = (const float*)d_in[4];
    const float* Bq = (const float*)d_in[5];
    const float* Wk = (const float*)d_in[6];
    const float* bk = (const float*)d_in[7];
    const float* Ak = (const float*)d_in[8];
    const float* Bk = (const float*)d_in[9];
    const float* Wv = (const float*)d_in[10];
    const float* bv = (const float*)d_in[11];
    const float* Av = (const float*)d_in[12];
    const float* Bv = (const float*)d_in[13];
    float* out = (float*)d_out;

    // 1) fold LoRA (truncated) + truncate X
    fold_lora_kernel<<<(3 * HID * HID + 255) / 256, 256>>>(Wq, Aq, Bq, Wk, Ak, Bk, Wv, Av, Bv);
    trunc_x_kernel<<<(BB * TT * HID / 4 + 255) / 256, 256>>>(X);

    // 2) fused QKV projection (tf32 mma.sync, CVT-free mainloop)
    cudaFuncSetAttribute(qkv_gemm_mma, cudaFuncAttributeMaxDynamicSharedMemorySize, GEMM_SMEM);
    qkv_gemm_mma<<<dim3(3 * HID / 128, BB * TT / 128), 256, GEMM_SMEM>>>(bq, bk, bv);

    // 3) causal flash attention (warp-local softmax, cp.async pipeline)
    cudaFuncSetAttribute(attn_mma, cudaFuncAttributeMaxDynamicSharedMemorySize, ATTN_SMEM);
    attn_mma<<<dim3(TT / QR, NH, BB), 256, ATTN_SMEM>>>(mask, out);
    (void)in_sizes; (void)n_in; (void)out_size;
}

// round 7
// speedup vs baseline: 8.5180x; 1.9654x over previous
#include <cuda_runtime.h>
#include <cuda_fp16.h>
#include <math.h>
#include <cstdint>

// Problem constants
#define HID 1024
#define NH  16
#define HD  64
#define BB  4
#define TT  2048
#define RR  8
#define SCALING 2.0f

// Scratch (device globals; no allocation allowed)
__device__ __half g_Weff[3 * HID * HID];        // fp16 folded weights [3072][1024] (K contiguous)
__device__ __half g_Xh[BB * TT * HID];          // fp16 X
// Q,K: [mat][b][h][t][d] fp16 (Q pre-scaled by 1/8).  V: [b][h][d][t] fp16 (transposed).
__device__ __half g_QKVh[3 * BB * NH * TT * HD];

// ---------------------------------------------------------------------------
// helpers
// ---------------------------------------------------------------------------
__device__ __forceinline__ uint32_t smem_u32(const void* p) {
    uint32_t a;
    asm("{ .reg .u64 t; cvta.to.shared.u64 t, %1; cvt.u32.u64 %0, t; }" : "=r"(a) : "l"(p));
    return a;
}
__device__ __forceinline__ void mma_f16(float c[4], uint32_t a0, uint32_t a1, uint32_t a2, uint32_t a3,
                                        uint32_t b0, uint32_t b1) {
    asm volatile(
        "mma.sync.aligned.m16n8k16.row.col.f32.f16.f16.f32 "
        "{%0,%1,%2,%3},{%4,%5,%6,%7},{%8,%9},{%0,%1,%2,%3};"
        : "+f"(c[0]), "+f"(c[1]), "+f"(c[2]), "+f"(c[3])
        : "r"(a0), "r"(a1), "r"(a2), "r"(a3), "r"(b0), "r"(b1));
}
__device__ __forceinline__ uint32_t pack_h2(float a, float b) {
    __half2 h = __floats2half2_rn(a, b);
    return *(uint32_t*)&h;
}
__device__ __forceinline__ void cp_async16(uint32_t smem, const void* gmem) {
    asm volatile("cp.async.cg.shared.global [%0], [%1], 16;" :: "r"(smem), "l"(gmem));
}
#define CP_COMMIT() asm volatile("cp.async.commit_group;" ::: "memory")
template <int N> __device__ __forceinline__ void cp_wait() {
    asm volatile("cp.async.wait_group %0;" :: "n"(N) : "memory");
}

// ---------------------------------------------------------------------------
// Kernel 1a: fold LoRA into dense weights (fp16 output)
// ---------------------------------------------------------------------------
__global__ void fold_lora_kernel(const float* __restrict__ W0, const float* __restrict__ A0, const float* __restrict__ B0,
                                 const float* __restrict__ W1, const float* __restrict__ A1, const float* __restrict__ B1,
                                 const float* __restrict__ W2, const float* __restrict__ A2, const float* __restrict__ B2) {
    int idx = blockIdx.x * blockDim.x + threadIdx.x;
    if (idx >= 3 * HID * HID) return;
    int mat = idx >> 20;
    int oi  = idx & (HID * HID - 1);
    int o   = oi >> 10;
    int i   = oi & 1023;
    const float* W = (mat == 0) ? W0 : (mat == 1) ? W1 : W2;
    const float* A = (mat == 0) ? A0 : (mat == 1) ? A1 : A2;
    const float* Bm = (mat == 0) ? B0 : (mat == 1) ? B1 : B2;
    float acc = W[oi];
#pragma unroll
    for (int r = 0; r < RR; r++)
        acc += SCALING * Bm[o * RR + r] * A[r * HID + i];
    g_Weff[idx] = __float2half_rn(acc);
}

// ---------------------------------------------------------------------------
// Kernel 1b: convert X to fp16
// ---------------------------------------------------------------------------
__global__ void trunc_x_kernel(const float* __restrict__ X) {
    int i = blockIdx.x * blockDim.x + threadIdx.x;   // float4 index
    if (i >= BB * TT * HID / 4) return;
    float4 v = ((const float4*)X)[i];
    uint2 o;
    o.x = pack_h2(v.x, v.y);
    o.y = pack_h2(v.z, v.w);
    ((uint2*)g_Xh)[i] = o;
}

// ---------------------------------------------------------------------------
// Kernel 2: QKV GEMM via mma.sync fp16 (m16n8k16).
// BM=BN=128, BK=32, 3-stage cp.async. 8 warps 2(M)x4(N), warp tile 64x32.
// Epilogue: bias, Q pre-scale, fp16 store; V stored transposed [d][t].
// ---------------------------------------------------------------------------
#define BKG 32
#define GSTAGES 3
#define ASTR 40                                  // halves per row (80B)
#define STG_BYTES (2 * 128 * ASTR * 2)           // A + B per stage = 20480
#define GEMM_SMEM (GSTAGES * STG_BYTES)          // 61440

__global__ void __launch_bounds__(256, 2)
qkv_gemm_mma(const float* __restrict__ bq, const float* __restrict__ bk, const float* __restrict__ bv) {
    extern __shared__ __half smh[];
    uint32_t sbase = smem_u32(smh);

    int tid = threadIdx.x;
    int w    = tid >> 5;
    int lane = tid & 31;
    int gid  = lane >> 2;
    int tid4 = lane & 3;
    int wm = w & 1;
    int wn = w >> 1;

    int m0b = blockIdx.y * 128;
    int n0b = blockIdx.x * 128;
    const __half* Wp = g_Weff;
    const __half* Xp = g_Xh;

    auto load_stage = [&](int kt, int slot) {
        int k0 = kt * BKG;
        uint32_t sa = sbase + (uint32_t)slot * STG_BYTES;
        uint32_t sb = sa + 128 * ASTR * 2;
#pragma unroll
        for (int i = 0; i < 2; i++) {
            int ch = tid + i * 256;               // 0..511
            int row = ch >> 2, c4 = ch & 3;
            uint32_t off = (uint32_t)(row * 80 + c4 * 16);
            cp_async16(sa + off, Xp + (size_t)(m0b + row) * HID + k0 + c4 * 8);
            cp_async16(sb + off, Wp + (size_t)(n0b + row) * HID + k0 + c4 * 8);
        }
        CP_COMMIT();
    };

    float acc[4][4][4];
#pragma unroll
    for (int mm = 0; mm < 4; mm++)
#pragma unroll
        for (int nn = 0; nn < 4; nn++)
#pragma unroll
            for (int j = 0; j < 4; j++) acc[mm][nn][j] = 0.f;

    load_stage(0, 0);
    load_stage(1, 1);

    const int NKT = HID / BKG;
    for (int kt = 0; kt < NKT; kt++) {
        int slot = kt % GSTAGES;
        if (kt >= NKT - 2) cp_wait<0>(); else cp_wait<1>();
        __syncthreads();
        if (kt + 2 < NKT) load_stage(kt + 2, (kt + 2) % GSTAGES);

        const __half* As = smh + slot * (STG_BYTES / 2) + (wm * 64) * ASTR;
        const __half* Bs = smh + slot * (STG_BYTES / 2) + 128 * ASTR + (wn * 32) * ASTR;
#pragma unroll
        for (int ks = 0; ks < 2; ks++) {
            int kc = ks * 16;
            uint32_t af[4][4];
#pragma unroll
            for (int mm = 0; mm < 4; mm++) {
                const __half* ar = As + (mm * 16 + gid) * ASTR + kc + 2 * tid4;
                af[mm][0] = *(const uint32_t*)ar;
                af[mm][1] = *(const uint32_t*)(ar + 8 * ASTR);
                af[mm][2] = *(const uint32_t*)(ar + 8);
                af[mm][3] = *(const uint32_t*)(ar + 8 * ASTR + 8);
            }
            uint32_t bf[4][2];
#pragma unroll
            for (int nn = 0; nn < 4; nn++) {
                const __half* br = Bs + (nn * 8 + gid) * ASTR + kc + 2 * tid4;
                bf[nn][0] = *(const uint32_t*)br;
                bf[nn][1] = *(const uint32_t*)(br + 8);
            }
#pragma unroll
            for (int mm = 0; mm < 4; mm++)
#pragma unroll
                for (int nn = 0; nn < 4; nn++)
                    mma_f16(acc[mm][nn], af[mm][0], af[mm][1], af[mm][2], af[mm][3], bf[nn][0], bf[nn][1]);
        }
    }

    // epilogue
#pragma unroll
    for (int nn = 0; nn < 4; nn++) {
        int c = n0b + wn * 32 + nn * 8 + tid4 * 2;
        int mat = c >> 10;
        int o = c & 1023;
        const float* bias = (mat == 0) ? bq : (mat == 1) ? bk : bv;
        float b0v = bias[o], b1v = bias[o + 1];
        float scl = (mat == 0) ? 0.125f : 1.0f;
        int h = o >> 6, d = o & 63;
#pragma unroll
        for (int mm = 0; mm < 4; mm++) {
#pragma unroll
            for (int half_ : {0, 1}) {
                int m = m0b + wm * 64 + mm * 16 + gid + half_ * 8;
                int bi = m >> 11, t = m & 2047;
                float v0 = (acc[mm][nn][2 * half_ + 0] + b0v) * scl;
                float v1 = (acc[mm][nn][2 * half_ + 1] + b1v) * scl;
                if (mat == 2) {
                    // V transposed: [b][h][d][t]
                    __half* vb = g_QKVh + ((size_t)((2 * BB + bi) * NH + h)) * (TT * HD);
                    vb[(size_t)d * TT + t]       = __float2half_rn(v0);
                    vb[(size_t)(d + 1) * TT + t] = __float2half_rn(v1);
                } else {
                    __half* dst = g_QKVh + ((size_t)((mat * BB + bi) * NH + h) * TT + t) * HD + d;
                    *(uint32_t*)dst = pack_h2(v0, v1);
                }
            }
        }
    }
}

// ---------------------------------------------------------------------------
// Kernel 3: causal flash attention, fp16 mma. Q-tile 128, K-tile 64.
// 8 warps x 16 rows x 64 cols; warp-local softmax; Q in registers.
// 3-stage cp.async K/V; V pre-transposed in gmem. 2 CTAs/SM.
// ---------------------------------------------------------------------------
#define QR 128
#define KTL 64
#define STK 72                                   // halves per row (144B)
#define NSTG 3
#define PB  (QR * STK * 2)                       // 18432
#define KSTGB (KTL * STK * 2)                    // 9216
#define OFF_P 0
#define OFF_K PB
#define OFF_V (PB + NSTG * KSTGB)
#define ATTN_SMEM (PB + 2 * NSTG * KSTGB)        // 73728

__global__ void __launch_bounds__(256, 2)
attn_mma(const float* __restrict__ mask, float* __restrict__ out) {
    extern __shared__ __half smh[];
    uint32_t sb = smem_u32(smh);

    int qt = gridDim.x - 1 - blockIdx.x;   // heavy blocks first
    int h  = blockIdx.y;
    int b  = blockIdx.z;

    const __half* Qg  = g_QKVh + (size_t)((0 * BB + b) * NH + h) * TT * HD;
    const __half* Kg  = g_QKVh + (size_t)((1 * BB + b) * NH + h) * TT * HD;
    const __half* Vtg = g_QKVh + (size_t)((2 * BB + b) * NH + h) * (TT * HD); // [d][t]
    const float* maskb = mask + (size_t)b * TT;

    int tid = threadIdx.x;
    int w    = tid >> 5;
    int lane = tid & 31;
    int gid  = lane >> 2;
    int tid4 = lane & 3;
    int rowb = w * 16;

    int nkt = 2 * (qt + 1);
    const int q0 = qt * QR + rowb + gid;
    const int q1 = q0 + 8;

    auto loadKV = [&](int kt_) {
        int s = kt_ % NSTG;
#pragma unroll
        for (int i = 0; i < 2; i++) {
            int ch = tid + i * 256;               // 0..511
            int r = ch >> 3, c = ch & 7;
            cp_async16(sb + OFF_K + s * KSTGB + r * 144 + c * 16,
                       Kg + (size_t)(kt_ * KTL + r) * HD + c * 8);
        }
#pragma unroll
        for (int i = 0; i < 2; i++) {
            int ch = tid + i * 256;
            int r = ch >> 3, c = ch & 7;           // r = d-row, c*8 = t within tile
            cp_async16(sb + OFF_V + s * KSTGB + r * 144 + c * 16,
                       Vtg + (size_t)r * TT + kt_ * KTL + c * 8);
        }
        CP_COMMIT();
    };

    // Q fragments in registers (Q pre-scaled by 1/8 at GEMM epilogue)
    uint32_t qf[4][4];
#pragma unroll
    for (int ks = 0; ks < 4; ks++) {
        int kc = ks * 16;
        qf[ks][0] = *(const uint32_t*)&Qg[(size_t)q0 * HD + kc + 2 * tid4];
        qf[ks][1] = *(const uint32_t*)&Qg[(size_t)q1 * HD + kc + 2 * tid4];
        qf[ks][2] = *(const uint32_t*)&Qg[(size_t)q0 * HD + kc + 8 + 2 * tid4];
        qf[ks][3] = *(const uint32_t*)&Qg[(size_t)q1 * HD + kc + 8 + 2 * tid4];
    }

    loadKV(0);
    if (nkt > 1) loadKV(1);

    float cO[8][4];
#pragma unroll
    for (int nn = 0; nn < 8; nn++)
#pragma unroll
        for (int j = 0; j < 4; j++) cO[nn][j] = 0.f;
    float m0 = -INFINITY, m1 = -INFINITY, l0 = 0.f, l1 = 0.f;

    for (int kt = 0; kt < nkt; kt++) {
        if (kt + 1 < nkt) cp_wait<1>(); else cp_wait<0>();
        __syncthreads();
        if (kt + 2 < nkt) loadKV(kt + 2);

        int stg = kt % NSTG;
        const __half* Ks = smh + (OFF_K + stg * KSTGB) / 2;
        const __half* Vs = smh + (OFF_V + stg * KSTGB) / 2;
        __half* Ps = smh + OFF_P / 2;

        // ---- S = Q @ K^T ----
        float cS[8][4];
#pragma unroll
        for (int nn = 0; nn < 8; nn++)
#pragma unroll
            for (int j = 0; j < 4; j++) cS[nn][j] = 0.f;
#pragma unroll
        for (int ks = 0; ks < 4; ks++) {
            int kc = ks * 16;
#pragma unroll
            for (int nn = 0; nn < 8; nn++) {
                const __half* kr = Ks + (nn * 8 + gid) * STK + kc + 2 * tid4;
                mma_f16(cS[nn], qf[ks][0], qf[ks][1], qf[ks][2], qf[ks][3],
                        *(const uint32_t*)kr, *(const uint32_t*)(kr + 8));
            }
        }

        // ---- mask + causal ----
        int colb0 = kt * KTL;
        bool diag = (kt >= 2 * qt);
#pragma unroll
        for (int nn = 0; nn < 8; nn++) {
            int c = colb0 + nn * 8 + 2 * tid4;
            float mk0 = __ldg(&maskb[c]);
            float mk1 = __ldg(&maskb[c + 1]);
            cS[nn][0] += mk0; cS[nn][1] += mk1;
            cS[nn][2] += mk0; cS[nn][3] += mk1;
            if (diag) {
                if (c     > q0) cS[nn][0] = -INFINITY;
                if (c + 1 > q0) cS[nn][1] = -INFINITY;
                if (c     > q1) cS[nn][2] = -INFINITY;
                if (c + 1 > q1) cS[nn][3] = -INFINITY;
            }
        }

        // ---- warp-local online softmax (quad reduction) ----
        float t0 = -INFINITY, t1 = -INFINITY;
#pragma unroll
        for (int nn = 0; nn < 8; nn++) {
            t0 = fmaxf(t0, fmaxf(cS[nn][0], cS[nn][1]));
            t1 = fmaxf(t1, fmaxf(cS[nn][2], cS[nn][3]));
        }
        t0 = fmaxf(t0, __shfl_xor_sync(0xffffffffu, t0, 1));
        t0 = fmaxf(t0, __shfl_xor_sync(0xffffffffu, t0, 2));
        t1 = fmaxf(t1, __shfl_xor_sync(0xffffffffu, t1, 1));
        t1 = fmaxf(t1, __shfl_xor_sync(0xffffffffu, t1, 2));
        float mn0 = fmaxf(m0, t0), mn1 = fmaxf(m1, t1);
        float cr0 = __expf(m0 - mn0), cr1 = __expf(m1 - mn1);
        m0 = mn0; m1 = mn1;
        float s0 = 0.f, s1 = 0.f;
#pragma unroll
        for (int nn = 0; nn < 8; nn++) {
            cS[nn][0] = __expf(cS[nn][0] - mn0); s0 += cS[nn][0];
            cS[nn][1] = __expf(cS[nn][1] - mn0); s0 += cS[nn][1];
            cS[nn][2] = __expf(cS[nn][2] - mn1); s1 += cS[nn][2];
            cS[nn][3] = __expf(cS[nn][3] - mn1); s1 += cS[nn][3];
        }
        s0 += __shfl_xor_sync(0xffffffffu, s0, 1);
        s0 += __shfl_xor_sync(0xffffffffu, s0, 2);
        s1 += __shfl_xor_sync(0xffffffffu, s1, 1);
        s1 += __shfl_xor_sync(0xffffffffu, s1, 2);
        l0 = l0 * cr0 + s0;
        l1 = l1 * cr1 + s1;
#pragma unroll
        for (int nn = 0; nn < 8; nn++) {
            cO[nn][0] *= cr0; cO[nn][1] *= cr0;
            cO[nn][2] *= cr1; cO[nn][3] *= cr1;
        }

        // ---- stage P as fp16 (warp-private rows) ----
#pragma unroll
        for (int nn = 0; nn < 8; nn++) {
            int cc = nn * 8 + 2 * tid4;
            *(uint32_t*)&Ps[(rowb + gid) * STK + cc]     = pack_h2(cS[nn][0], cS[nn][1]);
            *(uint32_t*)&Ps[(rowb + gid + 8) * STK + cc] = pack_h2(cS[nn][2], cS[nn][3]);
        }
        __syncwarp();

        // ---- O += P @ V  (V^T tiles: Vs[d][t]) ----
#pragma unroll
        for (int ks = 0; ks < 4; ks++) {
            int kc = ks * 16;
            const __half* pr0 = Ps + (rowb + gid) * STK + kc + 2 * tid4;
            const __half* pr1 = Ps + (rowb + gid + 8) * STK + kc + 2 * tid4;
            uint32_t a0 = *(const uint32_t*)pr0;
            uint32_t a1 = *(const uint32_t*)pr1;
            uint32_t a2 = *(const uint32_t*)(pr0 + 8);
            uint32_t a3 = *(const uint32_t*)(pr1 + 8);
#pragma unroll
            for (int nn = 0; nn < 8; nn++) {
                const __half* vr = Vs + (nn * 8 + gid) * STK + kc + 2 * tid4;
                mma_f16(cO[nn], a0, a1, a2, a3,
                        *(const uint32_t*)vr, *(const uint32_t*)(vr + 8));
            }
        }
        __syncwarp();
    }

    // ---- output ----
    float inv0 = 1.f / l0;
    float inv1 = 1.f / l1;
#pragma unroll
    for (int nn = 0; nn < 8; nn++) {
        int d = nn * 8 + tid4 * 2;
        float* o0p = out + ((size_t)(b * TT + q0)) * (NH * HD) + h * HD + d;
        *(float2*)o0p = make_float2(cO[nn][0] * inv0, cO[nn][1] * inv0);
        float* o1p = out + ((size_t)(b * TT + q1)) * (NH * HD) + h * HD + d;
        *(float2*)o1p = make_float2(cO[nn][2] * inv1, cO[nn][3] * inv1);
    }
}

// ---------------------------------------------------------------------------
extern "C" void kernel_launch(void* const* d_in, const int* in_sizes, int n_in,
                              void* d_out, int out_size) {
    const float* X    = (const float*)d_in[0];
    const float* mask = (const float*)d_in[1];
    const float* Wq = (const float*)d_in[2];
    const float* bq = (const float*)d_in[3];
    const float* Aq = (const float*)d_in[4];
    const float* Bq = (const float*)d_in[5];
    const float* Wk = (const float*)d_in[6];
    const float* bk = (const float*)d_in[7];
    const float* Ak = (const float*)d_in[8];
    const float* Bk = (const float*)d_in[9];
    const float* Wv = (const float*)d_in[10];
    const float* bv = (const float*)d_in[11];
    const float* Av = (const float*)d_in[12];
    const float* Bv = (const float*)d_in[13];
    float* out = (float*)d_out;

    // 1) fold LoRA (fp16) + convert X (fp16)
    fold_lora_kernel<<<(3 * HID * HID + 255) / 256, 256>>>(Wq, Aq, Bq, Wk, Ak, Bk, Wv, Av, Bv);
    trunc_x_kernel<<<(BB * TT * HID / 4 + 255) / 256, 256>>>(X);

    // 2) fused QKV projection (fp16 mma m16n8k16)
    cudaFuncSetAttribute(qkv_gemm_mma, cudaFuncAttributeMaxDynamicSharedMemorySize, GEMM_SMEM);
    qkv_gemm_mma<<<dim3(3 * HID / 128, BB * TT / 128), 256, GEMM_SMEM>>>(bq, bk, bv);

    // 3) causal flash attention (fp16 mma, 2 CTAs/SM)
    cudaFuncSetAttribute(attn_mma, cudaFuncAttributeMaxDynamicSharedMemorySize, ATTN_SMEM);
    attn_mma<<<dim3(TT / QR, NH, BB), 256, ATTN_SMEM>>>(mask, out);
    (void)in_sizes; (void)n_in; (void)out_size;
}

// round 8
// speedup vs baseline: 9.9650x; 1.1699x over previous
#include <cuda_runtime.h>
#include <cuda_fp16.h>
#include <math.h>
#include <cstdint>

// Problem constants
#define HID 1024
#define NH  16
#define HD  64
#define BB  4
#define TT  2048
#define RR  8
#define SCALING 2.0f
#define L2E 1.4426950408889634f

// Scratch (device globals; no allocation allowed)
__device__ __half g_Weff[3 * HID * HID];        // fp16 folded weights [3072][1024]
__device__ __half g_Xh[BB * TT * HID];          // fp16 X
// Q,K: [mat][b][h][t][d] fp16 (Q pre-scaled by 1/8).  V: [b][h][d][t] fp16 (transposed).
__device__ __half g_QKVh[3 * BB * NH * TT * HD];

// ---------------------------------------------------------------------------
// helpers
// ---------------------------------------------------------------------------
__device__ __forceinline__ uint32_t smem_u32(const void* p) {
    uint32_t a;
    asm("{ .reg .u64 t; cvta.to.shared.u64 t, %1; cvt.u32.u64 %0, t; }" : "=r"(a) : "l"(p));
    return a;
}
__device__ __forceinline__ void mma_f16(float c[4], uint32_t a0, uint32_t a1, uint32_t a2, uint32_t a3,
                                        uint32_t b0, uint32_t b1) {
    asm volatile(
        "mma.sync.aligned.m16n8k16.row.col.f32.f16.f16.f32 "
        "{%0,%1,%2,%3},{%4,%5,%6,%7},{%8,%9},{%0,%1,%2,%3};"
        : "+f"(c[0]), "+f"(c[1]), "+f"(c[2]), "+f"(c[3])
        : "r"(a0), "r"(a1), "r"(a2), "r"(a3), "r"(b0), "r"(b1));
}
__device__ __forceinline__ void ldm_x4(uint32_t& f0, uint32_t& f1, uint32_t& f2, uint32_t& f3, uint32_t addr) {
    asm volatile("ldmatrix.sync.aligned.m8n8.x4.shared.b16 {%0,%1,%2,%3}, [%4];"
                 : "=r"(f0), "=r"(f1), "=r"(f2), "=r"(f3) : "r"(addr));
}
__device__ __forceinline__ uint32_t ex2_h2(uint32_t x) {
    uint32_t r; asm volatile("ex2.approx.f16x2 %0, %1;" : "=r"(r) : "r"(x)); return r;
}
__device__ __forceinline__ uint32_t pack_h2(float a, float b) {
    __half2 h = __floats2half2_rn(a, b);
    return *(uint32_t*)&h;
}
__device__ __forceinline__ void cp_async16(uint32_t smem, const void* gmem) {
    asm volatile("cp.async.cg.shared.global [%0], [%1], 16;" :: "r"(smem), "l"(gmem));
}
#define CP_COMMIT() asm volatile("cp.async.commit_group;" ::: "memory")
template <int N> __device__ __forceinline__ void cp_wait() {
    asm volatile("cp.async.wait_group %0;" :: "n"(N) : "memory");
}

// ---------------------------------------------------------------------------
// Kernel 1a: fold LoRA into dense weights (fp16 output)
// ---------------------------------------------------------------------------
__global__ void fold_lora_kernel(const float* __restrict__ W0, const float* __restrict__ A0, const float* __restrict__ B0,
                                 const float* __restrict__ W1, const float* __restrict__ A1, const float* __restrict__ B1,
                                 const float* __restrict__ W2, const float* __restrict__ A2, const float* __restrict__ B2) {
    int idx = blockIdx.x * blockDim.x + threadIdx.x;
    if (idx >= 3 * HID * HID) return;
    int mat = idx >> 20;
    int oi  = idx & (HID * HID - 1);
    int o   = oi >> 10;
    int i   = oi & 1023;
    const float* W = (mat == 0) ? W0 : (mat == 1) ? W1 : W2;
    const float* A = (mat == 0) ? A0 : (mat == 1) ? A1 : A2;
    const float* Bm = (mat == 0) ? B0 : (mat == 1) ? B1 : B2;
    float acc = W[oi];
#pragma unroll
    for (int r = 0; r < RR; r++)
        acc += SCALING * Bm[o * RR + r] * A[r * HID + i];
    g_Weff[idx] = __float2half_rn(acc);
}

// ---------------------------------------------------------------------------
// Kernel 1b: convert X to fp16
// ---------------------------------------------------------------------------
__global__ void trunc_x_kernel(const float* __restrict__ X) {
    int i = blockIdx.x * blockDim.x + threadIdx.x;
    if (i >= BB * TT * HID / 4) return;
    float4 v = ((const float4*)X)[i];
    uint2 o;
    o.x = pack_h2(v.x, v.y);
    o.y = pack_h2(v.z, v.w);
    ((uint2*)g_Xh)[i] = o;
}

// ---------------------------------------------------------------------------
// Kernel 2: QKV GEMM via mma.sync fp16 + ldmatrix. BM=BN=128, BK=32, 4 stages.
// ---------------------------------------------------------------------------
#define GSTAGES 4
#define ASTR 40
#define STG_BYTES (2 * 128 * ASTR * 2)           // 20480
#define GEMM_SMEM (GSTAGES * STG_BYTES)          // 81920

__global__ void __launch_bounds__(256, 2)
qkv_gemm_mma(const float* __restrict__ bq, const float* __restrict__ bk, const float* __restrict__ bv) {
    extern __shared__ __half smh[];
    uint32_t sbase = smem_u32(smh);

    int tid = threadIdx.x;
    int w    = tid >> 5;
    int lane = tid & 31;
    int gid  = lane >> 2;
    int tid4 = lane & 3;
    int wm = w & 1;
    int wn = w >> 1;
    int j = lane >> 3, r = lane & 7;
    // ldmatrix lane offsets (bytes)
    uint32_t offA = (uint32_t)(((j & 1) * 8 + r) * ASTR + (j >> 1) * 8) * 2;
    uint32_t offB = (uint32_t)(((j >> 1) * 8 + r) * ASTR + (j & 1) * 8) * 2;

    int m0b = blockIdx.y * 128;
    int n0b = blockIdx.x * 128;
    const __half* Wp = g_Weff;
    const __half* Xp = g_Xh;

    auto load_stage = [&](int kt, int slot) {
        int k0 = kt * 32;
        uint32_t sa = sbase + (uint32_t)slot * STG_BYTES;
        uint32_t sb = sa + 128 * ASTR * 2;
#pragma unroll
        for (int i = 0; i < 2; i++) {
            int ch = tid + i * 256;
            int row = ch >> 2, c4 = ch & 3;
            uint32_t off = (uint32_t)(row * 80 + c4 * 16);
            cp_async16(sa + off, Xp + (size_t)(m0b + row) * HID + k0 + c4 * 8);
            cp_async16(sb + off, Wp + (size_t)(n0b + row) * HID + k0 + c4 * 8);
        }
        CP_COMMIT();
    };

    float acc[4][4][4];
#pragma unroll
    for (int mm = 0; mm < 4; mm++)
#pragma unroll
        for (int nn = 0; nn < 4; nn++)
#pragma unroll
            for (int jj = 0; jj < 4; jj++) acc[mm][nn][jj] = 0.f;

    load_stage(0, 0);
    load_stage(1, 1);
    load_stage(2, 2);

    const int NKT = HID / 32;   // 32
    for (int kt = 0; kt < NKT; kt++) {
        int slot = kt & (GSTAGES - 1);
        if (kt <= NKT - 3) cp_wait<2>(); else if (kt == NKT - 2) cp_wait<1>(); else cp_wait<0>();
        __syncthreads();
        if (kt + 3 < NKT) load_stage(kt + 3, (kt + 3) & (GSTAGES - 1));

        uint32_t aB = sbase + slot * STG_BYTES + (uint32_t)(wm * 64) * ASTR * 2 + offA;
        uint32_t bB = sbase + slot * STG_BYTES + 128 * ASTR * 2 + (uint32_t)(wn * 32) * ASTR * 2 + offB;
#pragma unroll
        for (int ks = 0; ks < 2; ks++) {
            uint32_t af[4][4];
#pragma unroll
            for (int mm = 0; mm < 4; mm++)
                ldm_x4(af[mm][0], af[mm][1], af[mm][2], af[mm][3],
                       aB + (uint32_t)(mm * 16 * ASTR + ks * 16) * 2);
            uint32_t bf[4][2];
#pragma unroll
            for (int p = 0; p < 2; p++)
                ldm_x4(bf[2 * p][0], bf[2 * p][1], bf[2 * p + 1][0], bf[2 * p + 1][1],
                       bB + (uint32_t)(p * 16 * ASTR + ks * 16) * 2);
#pragma unroll
            for (int mm = 0; mm < 4; mm++)
#pragma unroll
                for (int nn = 0; nn < 4; nn++)
                    mma_f16(acc[mm][nn], af[mm][0], af[mm][1], af[mm][2], af[mm][3], bf[nn][0], bf[nn][1]);
        }
    }

    // epilogue
#pragma unroll
    for (int nn = 0; nn < 4; nn++) {
        int c = n0b + wn * 32 + nn * 8 + tid4 * 2;
        int mat = c >> 10;
        int o = c & 1023;
        const float* bias = (mat == 0) ? bq : (mat == 1) ? bk : bv;
        float b0v = bias[o], b1v = bias[o + 1];
        float scl = (mat == 0) ? 0.125f : 1.0f;
        int h = o >> 6, d = o & 63;
#pragma unroll
        for (int mm = 0; mm < 4; mm++) {
#pragma unroll
            for (int half_ : {0, 1}) {
                int m = m0b + wm * 64 + mm * 16 + gid + half_ * 8;
                int bi = m >> 11, t = m & 2047;
                float v0 = (acc[mm][nn][2 * half_ + 0] + b0v) * scl;
                float v1 = (acc[mm][nn][2 * half_ + 1] + b1v) * scl;
                if (mat == 2) {
                    __half* vb = g_QKVh + ((size_t)((2 * BB + bi) * NH + h)) * (TT * HD);
                    vb[(size_t)d * TT + t]       = __float2half_rn(v0);
                    vb[(size_t)(d + 1) * TT + t] = __float2half_rn(v1);
                } else {
                    __half* dst = g_QKVh + ((size_t)((mat * BB + bi) * NH + h) * TT + t) * HD + d;
                    *(uint32_t*)dst = pack_h2(v0, v1);
                }
            }
        }
    }
}

// ---------------------------------------------------------------------------
// Kernel 3: causal flash attention. P in registers (C-frag == A-frag layout),
// ldmatrix K/V, ex2.f16x2 softmax, l via ones-MMA. 4-stage cp.async, 2 CTA/SM.
// ---------------------------------------------------------------------------
#define QR 128
#define KTL 64
#define STK 72
#define NSTG 4
#define KSTGB (KTL * STK * 2)                    // 9216
#define OFF_K 0
#define OFF_V (NSTG * KSTGB)
#define ATTN_SMEM (2 * NSTG * KSTGB)             // 73728

__global__ void __launch_bounds__(256, 2)
attn_mma(const float* __restrict__ mask, float* __restrict__ out) {
    extern __shared__ __half smh[];
    uint32_t sb = smem_u32(smh);

    int qt = gridDim.x - 1 - blockIdx.x;   // heavy blocks first
    int h  = blockIdx.y;
    int b  = blockIdx.z;

    const __half* Qg  = g_QKVh + (size_t)((0 * BB + b) * NH + h) * TT * HD;
    const __half* Kg  = g_QKVh + (size_t)((1 * BB + b) * NH + h) * TT * HD;
    const __half* Vtg = g_QKVh + (size_t)((2 * BB + b) * NH + h) * (TT * HD); // [d][t]
    const float* maskb = mask + (size_t)b * TT;

    int tid = threadIdx.x;
    int w    = tid >> 5;
    int lane = tid & 31;
    int gid  = lane >> 2;
    int tid4 = lane & 3;
    int rowb = w * 16;
    int j = lane >> 3, r = lane & 7;
    uint32_t lmoff = (uint32_t)(((j >> 1) * 8 + r) * STK + (j & 1) * 8) * 2;  // bytes

    int nkt = 2 * (qt + 1);
    const int q0 = qt * QR + rowb + gid;
    const int q1 = q0 + 8;

    auto loadKV = [&](int kt_) {
        int s = kt_ & (NSTG - 1);
#pragma unroll
        for (int i = 0; i < 2; i++) {
            int ch = tid + i * 256;
            int rr = ch >> 3, c = ch & 7;
            cp_async16(sb + OFF_K + s * KSTGB + rr * 144 + c * 16,
                       Kg + (size_t)(kt_ * KTL + rr) * HD + c * 8);
        }
#pragma unroll
        for (int i = 0; i < 2; i++) {
            int ch = tid + i * 256;
            int rr = ch >> 3, c = ch & 7;
            cp_async16(sb + OFF_V + s * KSTGB + rr * 144 + c * 16,
                       Vtg + (size_t)rr * TT + kt_ * KTL + c * 8);
        }
        CP_COMMIT();
    };

    // Q fragments in registers (Q pre-scaled by 1/8)
    uint32_t qf[4][4];
#pragma unroll
    for (int ks = 0; ks < 4; ks++) {
        int kc = ks * 16;
        qf[ks][0] = *(const uint32_t*)&Qg[(size_t)q0 * HD + kc + 2 * tid4];
        qf[ks][1] = *(const uint32_t*)&Qg[(size_t)q1 * HD + kc + 2 * tid4];
        qf[ks][2] = *(const uint32_t*)&Qg[(size_t)q0 * HD + kc + 8 + 2 * tid4];
        qf[ks][3] = *(const uint32_t*)&Qg[(size_t)q1 * HD + kc + 8 + 2 * tid4];
    }

    loadKV(0);
    if (nkt > 1) loadKV(1);
    if (nkt > 2) loadKV(2);

    float cO[8][4];
#pragma unroll
    for (int nn = 0; nn < 8; nn++)
#pragma unroll
        for (int jj = 0; jj < 4; jj++) cO[nn][jj] = 0.f;
    float m0 = -INFINITY, m1 = -INFINITY, l0 = 0.f, l1 = 0.f;
    const uint32_t ones_b = (gid == 0) ? 0x3C003C00u : 0u;

    for (int kt = 0; kt < nkt; kt++) {
        if (kt <= nkt - 3) cp_wait<2>(); else if (kt == nkt - 2) cp_wait<1>(); else cp_wait<0>();
        __syncthreads();
        if (kt + 3 < nkt) loadKV(kt + 3);

        int stg = kt & (NSTG - 1);
        uint32_t kB = sb + OFF_K + stg * KSTGB + lmoff;
        uint32_t vB = sb + OFF_V + stg * KSTGB + lmoff;

        // ---- S = Q @ K^T ----
        float cS[8][4];
#pragma unroll
        for (int nn = 0; nn < 8; nn++)
#pragma unroll
            for (int jj = 0; jj < 4; jj++) cS[nn][jj] = 0.f;
#pragma unroll
        for (int ks = 0; ks < 4; ks++) {
#pragma unroll
            for (int p = 0; p < 4; p++) {
                uint32_t f0, f1, f2, f3;
                ldm_x4(f0, f1, f2, f3, kB + (uint32_t)(p * 16 * STK + ks * 16) * 2);
                mma_f16(cS[2 * p],     qf[ks][0], qf[ks][1], qf[ks][2], qf[ks][3], f0, f1);
                mma_f16(cS[2 * p + 1], qf[ks][0], qf[ks][1], qf[ks][2], qf[ks][3], f2, f3);
            }
        }

        // ---- mask + causal ----
        int colb0 = kt * KTL;
        bool diag = (kt >= 2 * qt);
#pragma unroll
        for (int nn = 0; nn < 8; nn++) {
            int c = colb0 + nn * 8 + 2 * tid4;
            float mk0 = __ldg(&maskb[c]);
            float mk1 = __ldg(&maskb[c + 1]);
            cS[nn][0] += mk0; cS[nn][1] += mk1;
            cS[nn][2] += mk0; cS[nn][3] += mk1;
            if (diag) {
                if (c     > q0) cS[nn][0] = -3.0e4f;
                if (c + 1 > q0) cS[nn][1] = -3.0e4f;
                if (c     > q1) cS[nn][2] = -3.0e4f;
                if (c + 1 > q1) cS[nn][3] = -3.0e4f;
            }
        }

        // ---- warp-local online softmax: max via quad shfl ----
        float t0 = -INFINITY, t1 = -INFINITY;
#pragma unroll
        for (int nn = 0; nn < 8; nn++) {
            t0 = fmaxf(t0, fmaxf(cS[nn][0], cS[nn][1]));
            t1 = fmaxf(t1, fmaxf(cS[nn][2], cS[nn][3]));
        }
        t0 = fmaxf(t0, __shfl_xor_sync(0xffffffffu, t0, 1));
        t0 = fmaxf(t0, __shfl_xor_sync(0xffffffffu, t0, 2));
        t1 = fmaxf(t1, __shfl_xor_sync(0xffffffffu, t1, 1));
        t1 = fmaxf(t1, __shfl_xor_sync(0xffffffffu, t1, 2));
        float mn0 = fmaxf(m0, t0), mn1 = fmaxf(m1, t1);
        float cr0 = __expf(m0 - mn0), cr1 = __expf(m1 - mn1);
        m0 = mn0; m1 = mn1;
        float nm0 = mn0 * L2E, nm1 = mn1 * L2E;

        // ---- exp (base-2, fp16x2) -> P fragments directly ----
        uint32_t ph[8][2];
#pragma unroll
        for (int nn = 0; nn < 8; nn++) {
            float f0 = fmaf(cS[nn][0], L2E, -nm0);
            float f1 = fmaf(cS[nn][1], L2E, -nm0);
            float f2 = fmaf(cS[nn][2], L2E, -nm1);
            float f3 = fmaf(cS[nn][3], L2E, -nm1);
            ph[nn][0] = ex2_h2(pack_h2(f0, f1));
            ph[nn][1] = ex2_h2(pack_h2(f2, f3));
        }

        // ---- l via ones-MMA (col 0 holds row sum; valid on tid4==0) ----
        float cL[4] = {0.f, 0.f, 0.f, 0.f};
#pragma unroll
        for (int ks = 0; ks < 4; ks++)
            mma_f16(cL, ph[2 * ks][0], ph[2 * ks][1], ph[2 * ks + 1][0], ph[2 * ks + 1][1],
                    ones_b, ones_b);
        l0 = l0 * cr0 + cL[0];
        l1 = l1 * cr1 + cL[2];

        // ---- O = O*corr + P @ V ----
#pragma unroll
        for (int nn = 0; nn < 8; nn++) {
            cO[nn][0] *= cr0; cO[nn][1] *= cr0;
            cO[nn][2] *= cr1; cO[nn][3] *= cr1;
        }
#pragma unroll
        for (int ks = 0; ks < 4; ks++) {
#pragma unroll
            for (int p = 0; p < 4; p++) {
                uint32_t f0, f1, f2, f3;
                ldm_x4(f0, f1, f2, f3, vB + (uint32_t)(p * 16 * STK + ks * 16) * 2);
                mma_f16(cO[2 * p],     ph[2 * ks][0], ph[2 * ks][1], ph[2 * ks + 1][0], ph[2 * ks + 1][1], f0, f1);
                mma_f16(cO[2 * p + 1], ph[2 * ks][0], ph[2 * ks][1], ph[2 * ks + 1][0], ph[2 * ks + 1][1], f2, f3);
            }
        }
    }

    // broadcast l from quad leader (tid4==0)
    l0 = __shfl_sync(0xffffffffu, l0, lane & ~3);
    l1 = __shfl_sync(0xffffffffu, l1, lane & ~3);
    float inv0 = 1.f / l0;
    float inv1 = 1.f / l1;
#pragma unroll
    for (int nn = 0; nn < 8; nn++) {
        int d = nn * 8 + tid4 * 2;
        float* o0p = out + ((size_t)(b * TT + q0)) * (NH * HD) + h * HD + d;
        *(float2*)o0p = make_float2(cO[nn][0] * inv0, cO[nn][1] * inv0);
        float* o1p = out + ((size_t)(b * TT + q1)) * (NH * HD) + h * HD + d;
        *(float2*)o1p = make_float2(cO[nn][2] * inv1, cO[nn][3] * inv1);
    }
}

// ---------------------------------------------------------------------------
extern "C" void kernel_launch(void* const* d_in, const int* in_sizes, int n_in,
                              void* d_out, int out_size) {
    const float* X    = (const float*)d_in[0];
    const float* mask = (const float*)d_in[1];
    const float* Wq = (const float*)d_in[2];
    const float* bq = (const float*)d_in[3];
    const float* Aq = (const float*)d_in[4];
    const float* Bq = (const float*)d_in[5];
    const float* Wk = (const float*)d_in[6];
    const float* bk = (const float*)d_in[7];
    const float* Ak = (const float*)d_in[8];
    const float* Bk = (const float*)d_in[9];
    const float* Wv = (const float*)d_in[10];
    const float* bv = (const float*)d_in[11];
    const float* Av = (const float*)d_in[12];
    const float* Bv = (const float*)d_in[13];
    float* out = (float*)d_out;

    // 1) fold LoRA (fp16) + convert X (fp16)
    fold_lora_kernel<<<(3 * HID * HID + 255) / 256, 256>>>(Wq, Aq, Bq, Wk, Ak, Bk, Wv, Av, Bv);
    trunc_x_kernel<<<(BB * TT * HID / 4 + 255) / 256, 256>>>(X);

    // 2) fused QKV projection (fp16 mma + ldmatrix, 4-stage)
    cudaFuncSetAttribute(qkv_gemm_mma, cudaFuncAttributeMaxDynamicSharedMemorySize, GEMM_SMEM);
    qkv_gemm_mma<<<dim3(3 * HID / 128, BB * TT / 128), 256, GEMM_SMEM>>>(bq, bk, bv);

    // 3) causal flash attention (register-resident P, ldmatrix, ex2.f16x2)
    cudaFuncSetAttribute(attn_mma, cudaFuncAttributeMaxDynamicSharedMemorySize, ATTN_SMEM);
    attn_mma<<<dim3(TT / QR, NH, BB), 256, ATTN_SMEM>>>(mask, out);
    (void)in_sizes; (void)n_in; (void)out_size;
}